// round 4
// baseline (speedup 1.0000x reference)
#include <cuda_runtime.h>

#define N_S 50000
#define N_A 50000
#define E_A 800000
#define E_S 800000
#define HID 128
#define AGGA_C 20     // [sum_u(16), sum_pa(2), sum_dis(1), deg_a(1)]
#define AGGS_C 164    // [sum_x(32), sum_h(128), sum_ps(2), sum_dis(1), deg_s(1)]
#define KF 352        // folded feature width (padded)

// ---- scratch (__device__ globals; no allocation allowed) ----
__device__ float g_agg_a[N_S * AGGA_C];
__device__ float g_agg_s[N_S * AGGS_C];
__device__ float g_Wf[KF * HID];

__device__ int   g_deg_a[N_S], g_off_a[N_S + 1], g_cur_a[N_S];
__device__ int   g_deg_s[N_S], g_off_s[N_S + 1], g_cur_s[N_S];
__device__ int   g_csr_src_a[E_A];
__device__ float g_csr_dis_a[E_A];
__device__ int   g_csr_src_s[E_S];
__device__ float g_csr_dis_s[E_S];

// ---- packed f32x2 helpers ----
typedef unsigned long long ull;
__device__ __forceinline__ ull pack2(float lo, float hi) {
    ull r; asm("mov.b64 %0, {%1,%2};" : "=l"(r) : "f"(lo), "f"(hi)); return r;
}
__device__ __forceinline__ void unpack2(ull v, float& lo, float& hi) {
    asm("mov.b64 {%0,%1}, %2;" : "=f"(lo), "=f"(hi) : "l"(v));
}
__device__ __forceinline__ ull fma2(ull a, ull b, ull c) {
    ull d; asm("fma.rn.f32x2 %0, %1, %2, %3;" : "=l"(d) : "l"(a), "l"(b), "l"(c));
    return d;
}

// ---------------- CSR build ----------------
__global__ void zero_deg() {
    int i = blockIdx.x * blockDim.x + threadIdx.x;
    if (i < N_S) { g_deg_a[i] = 0; g_deg_s[i] = 0; }
}

__global__ void hist_kernel(const int* __restrict__ a_dst, const int* __restrict__ s_dst) {
    int i = blockIdx.x * blockDim.x + threadIdx.x;
    if (i < E_A) atomicAdd(&g_deg_a[a_dst[i]], 1);
    if (i < E_S) atomicAdd(&g_deg_s[s_dst[i]], 1);
}

// grid = 2 blocks of 1024 threads: block 0 scans deg_a, block 1 scans deg_s
__global__ void scan_kernel() {
    __shared__ int sh[1024];
    int* deg = blockIdx.x ? g_deg_s : g_deg_a;
    int* off = blockIdx.x ? g_off_s : g_off_a;
    int* cur = blockIdx.x ? g_cur_s : g_cur_a;
    const int CH = 49;  // 1024*49 >= 50000
    int t = threadIdx.x;
    int start = t * CH;
    int sum = 0;
    for (int i = 0; i < CH; i++) {
        int idx = start + i;
        if (idx < N_S) sum += deg[idx];
    }
    sh[t] = sum;
    __syncthreads();
    // Hillis-Steele inclusive scan
    for (int d = 1; d < 1024; d <<= 1) {
        int v = (t >= d) ? sh[t - d] : 0;
        __syncthreads();
        sh[t] += v;
        __syncthreads();
    }
    int base = sh[t] - sum;  // exclusive
    int run = base;
    for (int i = 0; i < CH; i++) {
        int idx = start + i;
        if (idx < N_S) {
            off[idx] = run;
            cur[idx] = run;
            run += deg[idx];
        }
    }
    if (t == 1023) off[N_S] = sh[1023];
}

__global__ void build_csr(const int* __restrict__ a_src, const int* __restrict__ a_dst,
                          const float* __restrict__ a_dis,
                          const int* __restrict__ s_src, const int* __restrict__ s_dst,
                          const float* __restrict__ s_dis) {
    int i = blockIdx.x * blockDim.x + threadIdx.x;
    if (i < E_A) {
        int p = atomicAdd(&g_cur_a[a_dst[i]], 1);
        g_csr_src_a[p] = a_src[i];
        g_csr_dis_a[p] = a_dis[i];
    }
    if (i < E_S) {
        int p = atomicAdd(&g_cur_s[s_dst[i]], 1);
        g_csr_src_s[p] = s_src[i];
        g_csr_dis_s[p] = s_dis[i];
    }
}

// ---------------- gathers (atomic-free) ----------------
// a2s: thread per (node, group). 5 float4 groups: g<4 -> u, g==4 -> [pa, dis, 1]
__global__ void gather_a2s(const float* __restrict__ u, const float* __restrict__ pa) {
    int id = blockIdx.x * blockDim.x + threadIdx.x;
    if (id >= N_S * 5) return;
    int node = id / 5;
    int g = id - node * 5;
    int beg = g_off_a[node], end = g_off_a[node + 1];
    float4 acc = make_float4(0.f, 0.f, 0.f, 0.f);
    if (g < 4) {
        for (int j = beg; j < end; j++) {
            int s = g_csr_src_a[j];
            float4 v = *(const float4*)(u + s * 16 + g * 4);
            acc.x += v.x; acc.y += v.y; acc.z += v.z; acc.w += v.w;
        }
    } else {
        for (int j = beg; j < end; j++) {
            int s = g_csr_src_a[j];
            float2 p = *(const float2*)(pa + s * 2);
            acc.x += p.x; acc.y += p.y; acc.z += g_csr_dis_a[j]; acc.w += 1.f;
        }
    }
    *(float4*)(g_agg_a + node * AGGA_C + g * 4) = acc;
}

// s2s: one warp per node. 41 float4 groups:
//  group lane (0..31): lane<8 -> x[lane*4], else h[(lane-8)*4]
//  group 32+lane (lanes 0..8): lane<8 -> h[(lane+24)*4], lane==8 -> [ps, dis, 1]
__global__ void gather_s2s(const float* __restrict__ x, const float* __restrict__ h,
                           const float* __restrict__ ps) {
    int gid = blockIdx.x * blockDim.x + threadIdx.x;
    int node = gid >> 5;
    int lane = gid & 31;
    if (node >= N_S) return;
    int beg = g_off_s[node], end = g_off_s[node + 1];
    float4 a0 = make_float4(0.f, 0.f, 0.f, 0.f);
    float4 a1 = make_float4(0.f, 0.f, 0.f, 0.f);
    for (int j = beg; j < end; j++) {
        int s = g_csr_src_s[j];  // uniform within warp
        float4 v;
        if (lane < 8) v = *(const float4*)(x + s * 32 + lane * 4);
        else          v = *(const float4*)(h + s * 128 + (lane - 8) * 4);
        a0.x += v.x; a0.y += v.y; a0.z += v.z; a0.w += v.w;
        if (lane < 8) {
            float4 w = *(const float4*)(h + s * 128 + (lane + 24) * 4);
            a1.x += w.x; a1.y += w.y; a1.z += w.z; a1.w += w.w;
        } else if (lane == 8) {
            float2 p = *(const float2*)(ps + s * 2);
            a1.x += p.x; a1.y += p.y; a1.z += g_csr_dis_s[j]; a1.w += 1.f;
        }
    }
    float* base = g_agg_s + node * AGGS_C;
    *(float4*)(base + lane * 4) = a0;
    if (lane < 8)       *(float4*)(base + (32 + lane) * 4) = a1;
    else if (lane == 8) *(float4*)(base + 160) = a1;
}

// ---------------- weight fold (unchanged, validated) ----------------
// Feature layout per node (K index):
//   0-1 ps | 2-129 h | 130-161 x | 162-180 agg_a[0..18] | 181 deg_a | 182-183 deg_a*ps
//   184-346 agg_s[0..162]/deg | 347 m | 348-349 m*ps | 350 const 1 | 351 pad 0
__global__ void fold_kernel(const float* __restrict__ Wu, const float* __restrict__ bu,
                            const float* __restrict__ Wx, const float* __restrict__ bx,
                            const float* __restrict__ Wupd, const float* __restrict__ bupd) {
    int r = blockIdx.x;       // 0..351
    int j = threadIdx.x;      // 0..127
    float outv;
    if (r < 130) {
        outv = Wupd[r * 128 + j];
    } else if (r < 162) {
        outv = Wupd[(386 + r - 130) * 128 + j];
    } else if (r < 184) {
        int i = r - 162;
        const float* v;
        if (i < 18)       v = Wu + i * 128;
        else if (i == 18) v = Wu + 20 * 128;
        else if (i == 19) v = bu;
        else              v = Wu + (i - 2) * 128;
        const float* Wsu = Wupd + 130 * 128;
        float acc = 0.f;
        for (int m = 0; m < 128; m++) acc += v[m] * Wsu[m * 128 + j];
        outv = acc;
    } else if (r < 350) {
        int i = r - 184;
        const float* v;
        if (i < 162)       v = Wx + i * 128;
        else if (i == 162) v = Wx + 164 * 128;
        else if (i == 163) v = bx;
        else               v = Wx + (i - 2) * 128;
        const float* Wmx = Wupd + 258 * 128;
        float acc = 0.f;
        for (int m = 0; m < 128; m++) acc += v[m] * Wmx[m * 128 + j];
        outv = acc;
    } else if (r == 350) {
        outv = bupd[j];
    } else {
        outv = 0.f;
    }
    g_Wf[r * 128 + j] = outv;
}

// ---------------- fused feature-build + GEMM ----------------
// out[50000,128] = F[50000,352] @ Wf[352,128]
// CTA tile: 128 nodes x 128 cols, 256 threads, 8x8 per thread, k-chunks of 16.
#define KC 16
#define BN 128
__device__ __forceinline__ float feature_val(int k, int node,
                                             const float* __restrict__ h,
                                             const float* __restrict__ x,
                                             const float* __restrict__ ps) {
    if (k < 2)        return ps[node * 2 + k];
    else if (k < 130) return h[node * 128 + (k - 2)];
    else if (k < 162) return x[node * 32 + (k - 130)];
    else if (k < 181) return g_agg_a[node * AGGA_C + (k - 162)];
    else if (k < 184) {
        float dega = g_agg_a[node * AGGA_C + 19];
        return (k == 181) ? dega : dega * ps[node * 2 + (k - 182)];
    } else if (k < 347) {
        float deg = g_agg_s[node * AGGS_C + 163];
        float inv = (deg > 0.f) ? (1.f / deg) : 0.f;
        return g_agg_s[node * AGGS_C + (k - 184)] * inv;
    } else if (k < 350) {
        float m = (g_agg_s[node * AGGS_C + 163] > 0.f) ? 1.f : 0.f;
        return (k == 347) ? m : m * ps[node * 2 + (k - 348)];
    } else if (k == 350) {
        return 1.f;
    }
    return 0.f;
}

__global__ __launch_bounds__(256, 2) void fused_gemm(
    const float* __restrict__ h, const float* __restrict__ x,
    const float* __restrict__ ps, float* __restrict__ out) {
    __shared__ float sA[KC * 132];   // k-major features: sA[k][n], stride 132
    __shared__ float sW[KC * 128];   // sW[k][c]
    int tid = threadIdx.x;
    int base = blockIdx.x * BN;
    int cg = tid & 15;   // col group: cols cg*8 .. cg*8+7
    int ng = tid >> 4;   // node group: nodes ng*8 .. ng*8+7

    ull acc[8][4];
#pragma unroll
    for (int n = 0; n < 8; n++)
#pragma unroll
        for (int p = 0; p < 4; p++) acc[n][p] = 0ULL;

    for (int kc = 0; kc < KF / KC; kc++) {
        __syncthreads();
        // load W chunk: 16x128 floats = 512 float4, 2 per thread
        {
            const float4* src = (const float4*)(g_Wf + kc * KC * 128);
            float4* dst = (float4*)sW;
            dst[tid]       = src[tid];
            dst[tid + 256] = src[tid + 256];
        }
        // build feature chunk: 128 nodes x 16 k. i = n*16 + klocal (k fastest for
        // coalesced h/x/agg reads per lane)
        for (int i = tid; i < BN * KC; i += 256) {
            int n = i >> 4;
            int kl = i & 15;
            int node = base + n;
            float val = (node < N_S) ? feature_val(kc * KC + kl, node, h, x, ps) : 0.f;
            sA[kl * 132 + n] = val;
        }
        __syncthreads();

#pragma unroll
        for (int kk = 0; kk < KC; kk++) {
            const float* ap = &sA[kk * 132 + ng * 8];
            float4 a0 = *(const float4*)ap;
            float4 a1 = *(const float4*)(ap + 4);
            const float* wp = &sW[kk * 128 + cg * 8];
            float4 w0 = *(const float4*)wp;
            float4 w1 = *(const float4*)(wp + 4);
            ull wq0 = pack2(w0.x, w0.y);
            ull wq1 = pack2(w0.z, w0.w);
            ull wq2 = pack2(w1.x, w1.y);
            ull wq3 = pack2(w1.z, w1.w);
            float av[8] = {a0.x, a0.y, a0.z, a0.w, a1.x, a1.y, a1.z, a1.w};
#pragma unroll
            for (int n = 0; n < 8; n++) {
                ull ap2 = pack2(av[n], av[n]);
                acc[n][0] = fma2(ap2, wq0, acc[n][0]);
                acc[n][1] = fma2(ap2, wq1, acc[n][1]);
                acc[n][2] = fma2(ap2, wq2, acc[n][2]);
                acc[n][3] = fma2(ap2, wq3, acc[n][3]);
            }
        }
    }

#pragma unroll
    for (int n = 0; n < 8; n++) {
        int node = base + ng * 8 + n;
        if (node < N_S) {
            float4 o0, o1;
            unpack2(acc[n][0], o0.x, o0.y);
            unpack2(acc[n][1], o0.z, o0.w);
            unpack2(acc[n][2], o1.x, o1.y);
            unpack2(acc[n][3], o1.z, o1.w);
            float* dst = out + node * 128 + cg * 8;
            *(float4*)dst = o0;
            *(float4*)(dst + 4) = o1;
        }
    }
}

extern "C" void kernel_launch(void* const* d_in, const int* in_sizes, int n_in,
                              void* d_out, int out_size) {
    const float* h       = (const float*)d_in[0];
    const float* x       = (const float*)d_in[1];
    const float* u       = (const float*)d_in[2];
    const float* ps      = (const float*)d_in[3];
    const float* pa      = (const float*)d_in[4];
    const float* dis_a   = (const float*)d_in[5];
    const float* dis_s   = (const float*)d_in[6];
    const int*   a2s_src = (const int*)d_in[7];
    const int*   a2s_dst = (const int*)d_in[8];
    const int*   s2s_src = (const int*)d_in[9];
    const int*   s2s_dst = (const int*)d_in[10];
    const float* Wu      = (const float*)d_in[11];
    const float* bu      = (const float*)d_in[12];
    const float* Wx      = (const float*)d_in[13];
    const float* bx      = (const float*)d_in[14];
    const float* Wupd    = (const float*)d_in[15];
    const float* bupd    = (const float*)d_in[16];
    float* out = (float*)d_out;

    // CSR build
    zero_deg<<<(N_S + 255) / 256, 256>>>();
    hist_kernel<<<(E_S + 255) / 256, 256>>>(a2s_dst, s2s_dst);
    scan_kernel<<<2, 1024>>>();
    build_csr<<<(E_S + 255) / 256, 256>>>(a2s_src, a2s_dst, dis_a,
                                          s2s_src, s2s_dst, dis_s);
    // aggregation (atomic-free gathers)
    gather_a2s<<<(N_S * 5 + 255) / 256, 256>>>(u, pa);
    gather_s2s<<<(N_S * 32 + 255) / 256, 256>>>(x, h, ps);
    // weight fold + fused GEMM
    fold_kernel<<<KF, 128>>>(Wu, bu, Wx, bx, Wupd, bupd);
    fused_gemm<<<(N_S + BN - 1) / BN, 256>>>(h, x, ps, out);
}

// round 5
// speedup vs baseline: 1.5129x; 1.5129x over previous
#include <cuda_runtime.h>

#define N_S 50000
#define N_A 50000
#define E_A 800000
#define E_S 800000
#define HID 128
#define AGGA_C 20     // [sum_u(16), sum_pa(2), sum_dis(1), deg_a(1)]
#define AGGS_C 164    // [sum_x(32), sum_h(128), sum_ps(2), sum_dis(1), deg_s(1)]
#define KF 352        // folded feature width (padded)

// ---- scratch (__device__ globals; no allocation allowed) ----
__device__ float g_agg_a[N_S * AGGA_C];
__device__ float g_agg_s[N_S * AGGS_C];
__device__ float g_Wf[KF * HID];

__device__ int   g_deg_a[N_S], g_off_a[N_S + 1], g_cur_a[N_S];
__device__ int   g_deg_s[N_S], g_off_s[N_S + 1], g_cur_s[N_S];
__device__ int   g_csr_src_a[E_A];
__device__ float g_csr_dis_a[E_A];
__device__ int   g_csr_src_s[E_S];
__device__ float g_csr_dis_s[E_S];

// ---- packed f32x2 helpers ----
typedef unsigned long long ull;
__device__ __forceinline__ ull pack2(float lo, float hi) {
    ull r; asm("mov.b64 %0, {%1,%2};" : "=l"(r) : "f"(lo), "f"(hi)); return r;
}
__device__ __forceinline__ void unpack2(ull v, float& lo, float& hi) {
    asm("mov.b64 {%0,%1}, %2;" : "=f"(lo), "=f"(hi) : "l"(v));
}
__device__ __forceinline__ ull fma2(ull a, ull b, ull c) {
    ull d; asm("fma.rn.f32x2 %0, %1, %2, %3;" : "=l"(d) : "l"(a), "l"(b), "l"(c));
    return d;
}

// ---------------- CSR build ----------------
__global__ void zero_deg() {
    int i = blockIdx.x * blockDim.x + threadIdx.x;
    if (i < N_S) { g_deg_a[i] = 0; g_deg_s[i] = 0; }
}

__global__ void hist_kernel(const int* __restrict__ a_dst, const int* __restrict__ s_dst) {
    int i = blockIdx.x * blockDim.x + threadIdx.x;
    if (i < E_A) atomicAdd(&g_deg_a[a_dst[i]], 1);
    if (i < E_S) atomicAdd(&g_deg_s[s_dst[i]], 1);
}

// grid = 2 blocks of 1024 threads: block 0 scans deg_a, block 1 scans deg_s
__global__ void scan_kernel() {
    __shared__ int sh[1024];
    int* deg = blockIdx.x ? g_deg_s : g_deg_a;
    int* off = blockIdx.x ? g_off_s : g_off_a;
    int* cur = blockIdx.x ? g_cur_s : g_cur_a;
    const int CH = 49;  // 1024*49 >= 50000
    int t = threadIdx.x;
    int start = t * CH;
    int sum = 0;
    for (int i = 0; i < CH; i++) {
        int idx = start + i;
        if (idx < N_S) sum += deg[idx];
    }
    sh[t] = sum;
    __syncthreads();
    for (int d = 1; d < 1024; d <<= 1) {
        int v = (t >= d) ? sh[t - d] : 0;
        __syncthreads();
        sh[t] += v;
        __syncthreads();
    }
    int base = sh[t] - sum;  // exclusive
    int run = base;
    for (int i = 0; i < CH; i++) {
        int idx = start + i;
        if (idx < N_S) {
            off[idx] = run;
            cur[idx] = run;
            run += deg[idx];
        }
    }
    if (t == 1023) off[N_S] = sh[1023];
}

__global__ void build_csr(const int* __restrict__ a_src, const int* __restrict__ a_dst,
                          const float* __restrict__ a_dis,
                          const int* __restrict__ s_src, const int* __restrict__ s_dst,
                          const float* __restrict__ s_dis) {
    int i = blockIdx.x * blockDim.x + threadIdx.x;
    if (i < E_A) {
        int p = atomicAdd(&g_cur_a[a_dst[i]], 1);
        g_csr_src_a[p] = a_src[i];
        g_csr_dis_a[p] = a_dis[i];
    }
    if (i < E_S) {
        int p = atomicAdd(&g_cur_s[s_dst[i]], 1);
        g_csr_src_s[p] = s_src[i];
        g_csr_dis_s[p] = s_dis[i];
    }
}

// ---------------- gathers (atomic-free, unrolled for MLP) ----------------
// a2s: thread per (node, group). 5 float4 groups: g<4 -> u, g==4 -> [pa, dis, 1]
__global__ void gather_a2s(const float* __restrict__ u, const float* __restrict__ pa) {
    int id = blockIdx.x * blockDim.x + threadIdx.x;
    if (id >= N_S * 5) return;
    int node = id / 5;
    int g = id - node * 5;
    int beg = g_off_a[node], end = g_off_a[node + 1];
    float4 acc = make_float4(0.f, 0.f, 0.f, 0.f);
    int j = beg;
    if (g < 4) {
        const float* ub = u + g * 4;
        for (; j + 4 <= end; j += 4) {
            int s0 = g_csr_src_a[j],     s1 = g_csr_src_a[j + 1];
            int s2 = g_csr_src_a[j + 2], s3 = g_csr_src_a[j + 3];
            float4 v0 = *(const float4*)(ub + s0 * 16);
            float4 v1 = *(const float4*)(ub + s1 * 16);
            float4 v2 = *(const float4*)(ub + s2 * 16);
            float4 v3 = *(const float4*)(ub + s3 * 16);
            acc.x += v0.x + v1.x + v2.x + v3.x;
            acc.y += v0.y + v1.y + v2.y + v3.y;
            acc.z += v0.z + v1.z + v2.z + v3.z;
            acc.w += v0.w + v1.w + v2.w + v3.w;
        }
        for (; j < end; j++) {
            int s = g_csr_src_a[j];
            float4 v = *(const float4*)(ub + s * 16);
            acc.x += v.x; acc.y += v.y; acc.z += v.z; acc.w += v.w;
        }
    } else {
        for (; j + 4 <= end; j += 4) {
            int s0 = g_csr_src_a[j],     s1 = g_csr_src_a[j + 1];
            int s2 = g_csr_src_a[j + 2], s3 = g_csr_src_a[j + 3];
            float2 p0 = *(const float2*)(pa + s0 * 2);
            float2 p1 = *(const float2*)(pa + s1 * 2);
            float2 p2 = *(const float2*)(pa + s2 * 2);
            float2 p3 = *(const float2*)(pa + s3 * 2);
            float d0 = g_csr_dis_a[j],     d1 = g_csr_dis_a[j + 1];
            float d2 = g_csr_dis_a[j + 2], d3 = g_csr_dis_a[j + 3];
            acc.x += p0.x + p1.x + p2.x + p3.x;
            acc.y += p0.y + p1.y + p2.y + p3.y;
            acc.z += d0 + d1 + d2 + d3;
            acc.w += 4.f;
        }
        for (; j < end; j++) {
            int s = g_csr_src_a[j];
            float2 p = *(const float2*)(pa + s * 2);
            acc.x += p.x; acc.y += p.y; acc.z += g_csr_dis_a[j]; acc.w += 1.f;
        }
    }
    *(float4*)(g_agg_a + node * AGGA_C + g * 4) = acc;
}

// s2s: one warp per node, edge loop unrolled by 4 for MLP.
//  group A (all lanes): lane<8 -> x[lane*4], else h[(lane-8)*4]
//  group B: lane<8 -> h[(lane+24)*4], lane==8 -> [ps, dis, 1]
__device__ __forceinline__ void s2s_edge_load(
    const float* __restrict__ x, const float* __restrict__ h,
    const float* __restrict__ ps, int j, int s, int lane,
    float4& v, float4& w) {
    if (lane < 8) {
        v = *(const float4*)(x + s * 32 + lane * 4);
        w = *(const float4*)(h + s * 128 + (lane + 24) * 4);
    } else {
        v = *(const float4*)(h + s * 128 + (lane - 8) * 4);
        if (lane == 8) {
            float2 p = *(const float2*)(ps + s * 2);
            w = make_float4(p.x, p.y, g_csr_dis_s[j], 1.f);
        } else {
            w = make_float4(0.f, 0.f, 0.f, 0.f);
        }
    }
}

__global__ __launch_bounds__(256) void gather_s2s(
    const float* __restrict__ x, const float* __restrict__ h,
    const float* __restrict__ ps) {
    int gid = blockIdx.x * blockDim.x + threadIdx.x;
    int node = gid >> 5;
    int lane = gid & 31;
    if (node >= N_S) return;
    int beg = g_off_s[node], end = g_off_s[node + 1];
    float4 a0 = make_float4(0.f, 0.f, 0.f, 0.f);
    float4 a1 = make_float4(0.f, 0.f, 0.f, 0.f);
    int j = beg;
    for (; j + 4 <= end; j += 4) {
        int s0 = g_csr_src_s[j],     s1 = g_csr_src_s[j + 1];
        int s2 = g_csr_src_s[j + 2], s3 = g_csr_src_s[j + 3];
        float4 v0, w0, v1, w1, v2, w2, v3, w3;
        s2s_edge_load(x, h, ps, j,     s0, lane, v0, w0);
        s2s_edge_load(x, h, ps, j + 1, s1, lane, v1, w1);
        s2s_edge_load(x, h, ps, j + 2, s2, lane, v2, w2);
        s2s_edge_load(x, h, ps, j + 3, s3, lane, v3, w3);
        a0.x += v0.x + v1.x + v2.x + v3.x;
        a0.y += v0.y + v1.y + v2.y + v3.y;
        a0.z += v0.z + v1.z + v2.z + v3.z;
        a0.w += v0.w + v1.w + v2.w + v3.w;
        a1.x += w0.x + w1.x + w2.x + w3.x;
        a1.y += w0.y + w1.y + w2.y + w3.y;
        a1.z += w0.z + w1.z + w2.z + w3.z;
        a1.w += w0.w + w1.w + w2.w + w3.w;
    }
    for (; j < end; j++) {
        int s = g_csr_src_s[j];
        float4 v, w;
        s2s_edge_load(x, h, ps, j, s, lane, v, w);
        a0.x += v.x; a0.y += v.y; a0.z += v.z; a0.w += v.w;
        a1.x += w.x; a1.y += w.y; a1.z += w.z; a1.w += w.w;
    }
    float* base = g_agg_s + node * AGGS_C;
    *(float4*)(base + lane * 4) = a0;
    if (lane < 8)       *(float4*)(base + (32 + lane) * 4) = a1;
    else if (lane == 8) *(float4*)(base + 160) = a1;
}

// ---------------- weight fold (unchanged, validated) ----------------
// Feature layout per node (K index):
//   0-1 ps | 2-129 h | 130-161 x | 162-180 agg_a[0..18] | 181 deg_a | 182-183 deg_a*ps
//   184-346 agg_s[0..162]/deg | 347 m | 348-349 m*ps | 350 const 1 | 351 pad 0
__global__ void fold_kernel(const float* __restrict__ Wu, const float* __restrict__ bu,
                            const float* __restrict__ Wx, const float* __restrict__ bx,
                            const float* __restrict__ Wupd, const float* __restrict__ bupd) {
    int r = blockIdx.x;       // 0..351
    int j = threadIdx.x;      // 0..127
    float outv;
    if (r < 130) {
        outv = Wupd[r * 128 + j];
    } else if (r < 162) {
        outv = Wupd[(386 + r - 130) * 128 + j];
    } else if (r < 184) {
        int i = r - 162;
        const float* v;
        if (i < 18)       v = Wu + i * 128;
        else if (i == 18) v = Wu + 20 * 128;
        else if (i == 19) v = bu;
        else              v = Wu + (i - 2) * 128;
        const float* Wsu = Wupd + 130 * 128;
        float acc = 0.f;
        for (int m = 0; m < 128; m++) acc += v[m] * Wsu[m * 128 + j];
        outv = acc;
    } else if (r < 350) {
        int i = r - 184;
        const float* v;
        if (i < 162)       v = Wx + i * 128;
        else if (i == 162) v = Wx + 164 * 128;
        else if (i == 163) v = bx;
        else               v = Wx + (i - 2) * 128;
        const float* Wmx = Wupd + 258 * 128;
        float acc = 0.f;
        for (int m = 0; m < 128; m++) acc += v[m] * Wmx[m * 128 + j];
        outv = acc;
    } else if (r == 350) {
        outv = bupd[j];
    } else {
        outv = 0.f;
    }
    g_Wf[r * 128 + j] = outv;
}

// ---------------- fused feature-build + GEMM ----------------
// out[50000,128] = F[50000,352] @ Wf[352,128]
#define KC 16
#define BN 128
__device__ __forceinline__ float feature_val(int k, int node,
                                             const float* __restrict__ h,
                                             const float* __restrict__ x,
                                             const float* __restrict__ ps) {
    if (k < 2)        return ps[node * 2 + k];
    else if (k < 130) return h[node * 128 + (k - 2)];
    else if (k < 162) return x[node * 32 + (k - 130)];
    else if (k < 181) return g_agg_a[node * AGGA_C + (k - 162)];
    else if (k < 184) {
        float dega = g_agg_a[node * AGGA_C + 19];
        return (k == 181) ? dega : dega * ps[node * 2 + (k - 182)];
    } else if (k < 347) {
        float deg = g_agg_s[node * AGGS_C + 163];
        float inv = (deg > 0.f) ? (1.f / deg) : 0.f;
        return g_agg_s[node * AGGS_C + (k - 184)] * inv;
    } else if (k < 350) {
        float m = (g_agg_s[node * AGGS_C + 163] > 0.f) ? 1.f : 0.f;
        return (k == 347) ? m : m * ps[node * 2 + (k - 348)];
    } else if (k == 350) {
        return 1.f;
    }
    return 0.f;
}

__global__ __launch_bounds__(256, 2) void fused_gemm(
    const float* __restrict__ h, const float* __restrict__ x,
    const float* __restrict__ ps, float* __restrict__ out) {
    __shared__ float sA[KC * 132];   // k-major features: sA[k][n], stride 132
    __shared__ float sW[KC * 128];   // sW[k][c]
    int tid = threadIdx.x;
    int base = blockIdx.x * BN;
    int cg = tid & 15;   // col group: cols cg*8 .. cg*8+7
    int ng = tid >> 4;   // node group: nodes ng*8 .. ng*8+7

    ull acc[8][4];
#pragma unroll
    for (int n = 0; n < 8; n++)
#pragma unroll
        for (int p = 0; p < 4; p++) acc[n][p] = 0ULL;

    for (int kc = 0; kc < KF / KC; kc++) {
        __syncthreads();
        {
            const float4* src = (const float4*)(g_Wf + kc * KC * 128);
            float4* dst = (float4*)sW;
            dst[tid]       = src[tid];
            dst[tid + 256] = src[tid + 256];
        }
        for (int i = tid; i < BN * KC; i += 256) {
            int n = i >> 4;
            int kl = i & 15;
            int node = base + n;
            float val = (node < N_S) ? feature_val(kc * KC + kl, node, h, x, ps) : 0.f;
            sA[kl * 132 + n] = val;
        }
        __syncthreads();

#pragma unroll
        for (int kk = 0; kk < KC; kk++) {
            const float* ap = &sA[kk * 132 + ng * 8];
            float4 a0 = *(const float4*)ap;
            float4 a1 = *(const float4*)(ap + 4);
            const float* wp = &sW[kk * 128 + cg * 8];
            float4 w0 = *(const float4*)wp;
            float4 w1 = *(const float4*)(wp + 4);
            ull wq0 = pack2(w0.x, w0.y);
            ull wq1 = pack2(w0.z, w0.w);
            ull wq2 = pack2(w1.x, w1.y);
            ull wq3 = pack2(w1.z, w1.w);
            float av[8] = {a0.x, a0.y, a0.z, a0.w, a1.x, a1.y, a1.z, a1.w};
#pragma unroll
            for (int n = 0; n < 8; n++) {
                ull ap2 = pack2(av[n], av[n]);
                acc[n][0] = fma2(ap2, wq0, acc[n][0]);
                acc[n][1] = fma2(ap2, wq1, acc[n][1]);
                acc[n][2] = fma2(ap2, wq2, acc[n][2]);
                acc[n][3] = fma2(ap2, wq3, acc[n][3]);
            }
        }
    }

#pragma unroll
    for (int n = 0; n < 8; n++) {
        int node = base + ng * 8 + n;
        if (node < N_S) {
            float4 o0, o1;
            unpack2(acc[n][0], o0.x, o0.y);
            unpack2(acc[n][1], o0.z, o0.w);
            unpack2(acc[n][2], o1.x, o1.y);
            unpack2(acc[n][3], o1.z, o1.w);
            float* dst = out + node * 128 + cg * 8;
            *(float4*)dst = o0;
            *(float4*)(dst + 4) = o1;
        }
    }
}

extern "C" void kernel_launch(void* const* d_in, const int* in_sizes, int n_in,
                              void* d_out, int out_size) {
    const float* h       = (const float*)d_in[0];
    const float* x       = (const float*)d_in[1];
    const float* u       = (const float*)d_in[2];
    const float* ps      = (const float*)d_in[3];
    const float* pa      = (const float*)d_in[4];
    const float* dis_a   = (const float*)d_in[5];
    const float* dis_s   = (const float*)d_in[6];
    const int*   a2s_src = (const int*)d_in[7];
    const int*   a2s_dst = (const int*)d_in[8];
    const int*   s2s_src = (const int*)d_in[9];
    const int*   s2s_dst = (const int*)d_in[10];
    const float* Wu      = (const float*)d_in[11];
    const float* bu      = (const float*)d_in[12];
    const float* Wx      = (const float*)d_in[13];
    const float* bx      = (const float*)d_in[14];
    const float* Wupd    = (const float*)d_in[15];
    const float* bupd    = (const float*)d_in[16];
    float* out = (float*)d_out;

    zero_deg<<<(N_S + 255) / 256, 256>>>();
    hist_kernel<<<(E_S + 255) / 256, 256>>>(a2s_dst, s2s_dst);
    scan_kernel<<<2, 1024>>>();
    build_csr<<<(E_S + 255) / 256, 256>>>(a2s_src, a2s_dst, dis_a,
                                          s2s_src, s2s_dst, dis_s);
    gather_a2s<<<(N_S * 5 + 255) / 256, 256>>>(u, pa);
    gather_s2s<<<(N_S * 32 + 255) / 256, 256>>>(x, h, ps);
    fold_kernel<<<KF, 128>>>(Wu, bu, Wx, bx, Wupd, bupd);
    fused_gemm<<<(N_S + BN - 1) / BN, 256>>>(h, x, ps, out);
}